// round 15
// baseline (speedup 1.0000x reference)
#include <cuda_runtime.h>
#include <cuda_fp16.h>
#include <math.h>

// Shapes (fixed by the problem)
#define B   128
#define N   196
#define C   768
#define CTR 64
#define NM  (N*N)          // 38416
#define VP  200            // padded token-dim length (halves), 16B-aligned rows
#define KH  64             // k-tile (halves) per pipeline stage
#define RS  72             // A smem row stride (halves); conflict-free ldmatrix
#define BS2 136            // B smem row stride for gemm_y trans tiles
// Dataflow: y = v @ x^T  (per batch, trans-ldmatrix on x[t][c]), out = y @ W^T + bias.

// Scratch (device globals: allocation-free rule)
__device__ float g_attn[B*CTR];
__device__ float g_qp[B*8*C];                    // partial column sums (7 used, pad 8)
__device__ __half g_xh[(size_t)B*N*C];           // fp16 x, natural [b][t][c]
__device__ __half g_wh[(size_t)C*C];             // fp16 proj_w [n][k]
__device__ __half g_v16[(size_t)B*N*VP];         // fp16 v, rows padded
__device__ __half g_y[(size_t)B*N*C];            // fp16 y = v@x^T, [b][t][c]

__device__ __forceinline__ void cp16(void* sdst, const void* gsrc, bool pred) {
    unsigned d = (unsigned)__cvta_generic_to_shared(sdst);
    int sz = pred ? 16 : 0;
    asm volatile("cp.async.cg.shared.global [%0], [%1], 16, %2;\n"
                 :: "r"(d), "l"(gsrc), "r"(sz));
}
__device__ __forceinline__ void cp_commit() {
    asm volatile("cp.async.commit_group;\n" ::: "memory");
}
__device__ __forceinline__ void cp_wait0() {
    asm volatile("cp.async.wait_group 0;\n" ::: "memory");
}
__device__ __forceinline__ void cp_wait1() {
    asm volatile("cp.async.wait_group 1;\n" ::: "memory");
}

#define MMA_F16(acc, af, bf)                                                  \
    asm volatile(                                                             \
        "mma.sync.aligned.m16n8k16.row.col.f32.f16.f16.f32 "                  \
        "{%0,%1,%2,%3}, {%4,%5,%6,%7}, {%8,%9}, {%0,%1,%2,%3};"               \
        : "+f"((acc)[0]), "+f"((acc)[1]), "+f"((acc)[2]), "+f"((acc)[3])      \
        : "r"((af)[0]), "r"((af)[1]), "r"((af)[2]), "r"((af)[3]),             \
          "r"((bf)[0]), "r"((bf)[1]))

#define LDM_X4(r0, r1, r2, r3, addr)                                          \
    asm volatile(                                                             \
        "ldmatrix.sync.aligned.m8n8.x4.shared.b16 {%0,%1,%2,%3}, [%4];"       \
        : "=r"(r0), "=r"(r1), "=r"(r2), "=r"(r3) : "r"(addr))

#define LDM_X4T(r0, r1, r2, r3, addr)                                         \
    asm volatile(                                                             \
        "ldmatrix.sync.aligned.m8n8.x4.trans.shared.b16 {%0,%1,%2,%3}, [%4];" \
        : "=r"(r0), "=r"(r1), "=r"(r2), "=r"(r3) : "r"(addr))

// ---------------------------------------------------------------------------
// K1: fused pre-pass, VECTORIZED. grid (B, 8).
//   j in 0..6: 28 tokens -> fp16 g_xh (float4 loads, uint2 stores) + col sums
//   j == 7  : proj_w -> fp16 slice (vectorized); zero t-pads of g_v16
// ---------------------------------------------------------------------------
__global__ void prep_kernel(const float* __restrict__ x,
                            const float* __restrict__ w) {
    const int b = blockIdx.x, j = blockIdx.y;
    const int tid = threadIdx.x;
    if (j < 7) {
        if (tid < 192) {                       // 192 threads x 4 channels = 768
            const int c = tid * 4;
            const int r0 = j * 28;
            const float* xb = x + (size_t)b*N*C;
            float s0 = 0.f, s1 = 0.f, s2 = 0.f, s3 = 0.f;
            #pragma unroll 4
            for (int n = 0; n < 28; n++) {
                size_t idx = (size_t)(r0+n)*C + c;
                float4 v4 = *(const float4*)&xb[idx];
                __half2 h[2];
                h[0] = __floats2half2_rn(v4.x, v4.y);
                h[1] = __floats2half2_rn(v4.z, v4.w);
                *(uint2*)&g_xh[(size_t)b*N*C + idx] = *(uint2*)h;
                s0 += v4.x; s1 += v4.y; s2 += v4.z; s3 += v4.w;
            }
            *(float4*)&g_qp[((size_t)b*8 + j)*C + c] =
                make_float4(s0, s1, s2, s3);
        }
    } else {
        const int base = b * (C*C / B);        // 4608 elements
        for (int i4 = tid; i4 < (C*C / B) / 4; i4 += 256) {
            float4 v4 = *(const float4*)&w[base + i4*4];
            __half2 h[2];
            h[0] = __floats2half2_rn(v4.x, v4.y);
            h[1] = __floats2half2_rn(v4.z, v4.w);
            *(uint2*)&g_wh[base + i4*4] = *(uint2*)h;
        }
        const int p0 = b * N;
        for (int i = tid; i < N; i += 256)
            *(unsigned long long*)&g_v16[(size_t)(p0 + i)*VP + N] = 0ull;
    }
}

// ---------------------------------------------------------------------------
// K2: finish mean, cosine-sim vs k_c (coalesced), softmax
// ---------------------------------------------------------------------------
__global__ void attn_kernel(const float* __restrict__ k_c) {
    const int b = blockIdx.x;
    __shared__ float q[C];
    __shared__ float red[256];
    __shared__ float sdot[4][CTR];
    __shared__ float skn[4][CTR];
    __shared__ float logits[CTR];
    const int tid = threadIdx.x;

    for (int c = tid; c < C; c += 256) {
        float s = 0.f;
        #pragma unroll
        for (int j = 0; j < 7; j++) s += g_qp[((size_t)b*8 + j)*C + c];
        q[c] = s * (1.0f/N);
    }
    __syncthreads();

    float ps = 0.f;
    for (int c = tid; c < C; c += 256) ps += q[c]*q[c];
    red[tid] = ps;
    __syncthreads();
    for (int s = 128; s > 0; s >>= 1) {
        if (tid < s) red[tid] += red[tid+s];
        __syncthreads();
    }
    const float qinv = 1.0f / fmaxf(sqrtf(red[0]), 1e-12f);

    {
        const int c = tid & 63, g = tid >> 6;
        float dot = 0.f, kn = 0.f;
        for (int k = g; k < C; k += 4) {
            float kv = k_c[k*CTR + c];
            dot += q[k]*kv;
            kn  += kv*kv;
        }
        sdot[g][c] = dot;
        skn[g][c]  = kn;
    }
    __syncthreads();
    if (tid < CTR) {
        float d = sdot[0][tid] + sdot[1][tid] + sdot[2][tid] + sdot[3][tid];
        float n = skn[0][tid]  + skn[1][tid]  + skn[2][tid]  + skn[3][tid];
        float kinv = 1.0f / fmaxf(sqrtf(n), 1e-12f);
        logits[tid] = d * qinv * kinv * 0.03608439182435161f;
    }
    __syncthreads();

    if (tid == 0) {
        float mx = -1e30f;
        #pragma unroll
        for (int c = 0; c < CTR; c++) mx = fmaxf(mx, logits[c]);
        float sum = 0.f;
        #pragma unroll
        for (int c = 0; c < CTR; c++) { float e = expf(logits[c]-mx); logits[c] = e; sum += e; }
        float inv = 1.0f/sum;
        #pragma unroll
        for (int c = 0; c < CTR; c++) g_attn[b*CTR + c] = logits[c]*inv;
    }
}

// ---------------------------------------------------------------------------
// K3: v[b][n][m] = sum_c attn[b,c] * v_c[c][n][m]  (fp16, padded rows)
// ---------------------------------------------------------------------------
__global__ void mix_kernel(const float* __restrict__ v_c) {
    __shared__ float a_s[32*CTR];
    const int tid = threadIdx.x;
    const int g   = blockIdx.y;
    for (int i = tid; i < 32*CTR; i += 256) a_s[i] = g_attn[g*32*CTR + i];
    __syncthreads();

    const int nm = blockIdx.x*256 + tid;
    if (nm >= NM) return;
    const int n = nm / N, m = nm - n * N;

    float vr[CTR];
    #pragma unroll
    for (int c = 0; c < CTR; c++) vr[c] = v_c[(size_t)c*NM + nm];

    for (int b = 0; b < 32; b++) {
        const float* ap = a_s + b*CTR;
        float acc = 0.f;
        #pragma unroll
        for (int c = 0; c < CTR; c++) acc += ap[c]*vr[c];
        g_v16[((size_t)(g*32 + b)*N + n)*VP + m] = __float2half(acc);
    }
}

// ---------------------------------------------------------------------------
// K4: y[b] = v[b] @ x[b]^T   (M=196 tokens, N=768 channels, K=196 tokens)
// A = g_v16[b] [m][k]; B = g_xh[b] [k=t][n=c] row-major via ldmatrix.trans.
// 8 warps, 64x32 warp tile, 3-stage cp.async ring. (R12-best version.)
// ---------------------------------------------------------------------------
#define ASTG (128*RS)           // A halves per stage
#define BSTG (64*BS2)           // B halves per stage
#define YSTG (ASTG + BSTG)      // stage stride (halves)

__global__ __launch_bounds__(256, 2)
void gemm_y_f16() {
    extern __shared__ __half smh[];
    const int b = blockIdx.z;
    const __half* A = g_v16 + (size_t)b*N*VP;
    __half* Y = g_y + (size_t)b*N*C;

    const int tid  = threadIdx.x;
    const int lane = tid & 31;
    const int w    = tid >> 5;
    const int wm   = (w & 1) * 64;
    const int wn   = (w >> 1) * 32;
    const int bm   = blockIdx.y * 128;     // 0 or 128
    const int bn   = blockIdx.x * 128;     // channel block

    const int lrow = tid >> 1;             // A loader: row 0..127
    const int lko  = (tid & 1) * 32;       // A loader: k base
    const int brow = tid >> 2;             // B loader: k-row 0..63
    const int bc0  = (tid & 3) * 32;       // B loader: col base

    const int gq = lane >> 2;
    const int tq = lane & 3;

    const int aRow  = wm + (lane & 7) + ((lane >> 3) & 1) * 8;  // + mi*16
    const int aK    = (lane >> 4) * 8;                          // + kb
    const int bRowT = (lane & 7) + ((lane >> 3) & 1) * 8;       // + kb (trans)
    const int bColT = (lane >> 4) * 8;                          // + wn + j*16

    float acc[4][4][4] = {};

    auto issue_load = [&](int s, int k0) {
        __half* As = smh + (size_t)s*YSTG;
        __half* Bs = As + ASTG;
        #pragma unroll
        for (int cch = 0; cch < 4; cch++) {
            int ko = lko + cch*8;
            cp16(&As[(size_t)lrow*RS + ko], &A[(size_t)(bm+lrow)*VP + k0 + ko],
                 (bm + lrow < N) && (k0 + ko + 8 <= VP));
        }
        const bool rok = (k0 + brow) < N;
        #pragma unroll
        for (int cch = 0; cch < 4; cch++) {
            int co = bc0 + cch*8;
            cp16(&Bs[(size_t)brow*BS2 + co],
                 &g_xh[((size_t)b*N + k0 + brow)*C + bn + co], rok);
        }
        cp_commit();
    };

    const int NITER = 4;        // K covers 0..255; invalid k zero-filled
    issue_load(0, 0);
    issue_load(1, KH);

    for (int it = 0; it < NITER; it++) {
        const int cur = it % 3;
        if (it + 2 < NITER) cp_wait1(); else cp_wait0();
        __syncthreads();
        if (it + 2 < NITER) issue_load((it + 2) % 3, (it + 2) * KH);

        const __half* Ac = smh + (size_t)cur*YSTG;
        const __half* Bc = Ac + ASTG;
        const unsigned Acs = (unsigned)__cvta_generic_to_shared(Ac);
        const unsigned Bcs = (unsigned)__cvta_generic_to_shared(Bc);
        #pragma unroll
        for (int ks = 0; ks < 4; ks++) {
            const int kb = ks * 16;
            unsigned af[4][4], bf[4][2];
            #pragma unroll
            for (int mi = 0; mi < 4; mi++)
                LDM_X4(af[mi][0], af[mi][1], af[mi][2], af[mi][3],
                       Acs + (unsigned)(((aRow + mi*16)*RS + kb + aK) * 2));
            #pragma unroll
            for (int j = 0; j < 2; j++)
                LDM_X4T(bf[2*j][0], bf[2*j][1], bf[2*j+1][0], bf[2*j+1][1],
                        Bcs + (unsigned)(((kb + bRowT)*BS2 + wn + j*16 + bColT) * 2));
            #pragma unroll
            for (int mi = 0; mi < 4; mi++)
                #pragma unroll
                for (int nj = 0; nj < 4; nj++)
                    MMA_F16(acc[mi][nj], af[mi], bf[nj]);
        }
    }

    // epilogue: fp16 y, coalesced half2; guard rows < 196
    #pragma unroll
    for (int mi = 0; mi < 4; mi++) {
        #pragma unroll
        for (int nj = 0; nj < 4; nj++) {
            int r  = bm + wm + mi*16 + gq;
            int cc = bn + wn + nj*8 + 2*tq;
            if (r < N)
                *(__half2*)&Y[(size_t)r*C + cc] =
                    __halves2half2(__float2half(acc[mi][nj][0]), __float2half(acc[mi][nj][1]));
            if (r + 8 < N)
                *(__half2*)&Y[(size_t)(r+8)*C + cc] =
                    __halves2half2(__float2half(acc[mi][nj][2]), __float2half(acc[mi][nj][3]));
        }
    }
}

// ---------------------------------------------------------------------------
// K5: out = y @ W^T + bias   (M=25088, N=768, K=768)
// fp16 mma m16n8k16 + ldmatrix, 8 warps, 64x32 warp tile, 3-stage ring.
// ---------------------------------------------------------------------------
__global__ __launch_bounds__(256, 2)
void gemm_out_f16(const float* __restrict__ bias,
                  float* __restrict__ OUT) {
    extern __shared__ __half smh[];
    const int tid  = threadIdx.x;
    const int lane = tid & 31;
    const int w    = tid >> 5;
    const int wm   = (w & 1) * 64;
    const int wn   = (w >> 1) * 32;
    const int bm   = blockIdx.y * 128;
    const int bn   = blockIdx.x * 128;

    const int lrow = tid >> 1;
    const int lko  = (tid & 1) * 32;

    const int gq = lane >> 2;
    const int tq = lane & 3;

    const int aRow = wm + (lane & 7) + ((lane >> 3) & 1) * 8;
    const int aK   = (lane >> 4) * 8;
    const int bN   = wn + (lane & 7) + (lane >> 4) * 8;
    const int bK   = ((lane >> 3) & 1) * 8;

    float acc[4][4][4] = {};

    auto issue_load = [&](int s, int k0) {
        __half* As = smh + (size_t)s*2*128*RS;
        __half* Bs = As + (size_t)128*RS;
        #pragma unroll
        for (int cch = 0; cch < 4; cch++) {
            int ko = lko + cch*8;
            cp16(&As[(size_t)lrow*RS + ko], &g_y[(size_t)(bm+lrow)*C + k0 + ko], true);
            cp16(&Bs[(size_t)lrow*RS + ko], &g_wh[(size_t)(bn+lrow)*C + k0 + ko], true);
        }
        cp_commit();
    };

    const int NITER = C / KH;   // 12
    issue_load(0, 0);
    issue_load(1, KH);

    for (int it = 0; it < NITER; it++) {
        const int cur = it % 3;
        if (it + 2 < NITER) cp_wait1(); else cp_wait0();
        __syncthreads();
        if (it + 2 < NITER) issue_load((it + 2) % 3, (it + 2) * KH);

        const __half* Ac = smh + (size_t)cur*2*128*RS;
        const __half* Bc = Ac + (size_t)128*RS;
        const unsigned Acs = (unsigned)__cvta_generic_to_shared(Ac);
        const unsigned Bcs = (unsigned)__cvta_generic_to_shared(Bc);
        #pragma unroll
        for (int ks = 0; ks < 4; ks++) {
            const int kb = ks * 16;
            unsigned af[4][4], bf[4][2];
            #pragma unroll
            for (int mi = 0; mi < 4; mi++)
                LDM_X4(af[mi][0], af[mi][1], af[mi][2], af[mi][3],
                       Acs + (unsigned)(((aRow + mi*16)*RS + kb + aK) * 2));
            LDM_X4(bf[0][0], bf[0][1], bf[1][0], bf[1][1],
                   Bcs + (unsigned)((bN*RS + kb + bK) * 2));
            LDM_X4(bf[2][0], bf[2][1], bf[3][0], bf[3][1],
                   Bcs + (unsigned)(((bN + 16)*RS + kb + bK) * 2));
            #pragma unroll
            for (int mi = 0; mi < 4; mi++)
                #pragma unroll
                for (int nj = 0; nj < 4; nj++)
                    MMA_F16(acc[mi][nj], af[mi], bf[nj]);
        }
    }

    // epilogue: plain coalesced fp32 + bias (all indices valid)
    #pragma unroll
    for (int mi = 0; mi < 4; mi++) {
        #pragma unroll
        for (int nj = 0; nj < 4; nj++) {
            int r  = bm + wm + mi*16 + gq;
            int cc = bn + wn + nj*8 + 2*tq;
            float b0 = bias[cc], b1 = bias[cc+1];
            *(float2*)&OUT[(size_t)r*C + cc] =
                make_float2(acc[mi][nj][0] + b0, acc[mi][nj][1] + b1);
            *(float2*)&OUT[(size_t)(r+8)*C + cc] =
                make_float2(acc[mi][nj][2] + b0, acc[mi][nj][3] + b1);
        }
    }
}

// ---------------------------------------------------------------------------
extern "C" void kernel_launch(void* const* d_in, const int* in_sizes, int n_in,
                              void* d_out, int out_size) {
    const float* x      = (const float*)d_in[0];   // (128,196,768)
    const float* k_c    = (const float*)d_in[1];   // (768,64)
    const float* v_c    = (const float*)d_in[2];   // (64,196,196)
    const float* proj_w = (const float*)d_in[3];   // (768,768)
    const float* proj_b = (const float*)d_in[4];   // (768,)
    float* out = (float*)d_out;

    const int SMEM_Y = 3*YSTG * (int)sizeof(__half);        // 107520
    const int SMEM_G = 3*2*128*RS * (int)sizeof(__half);    // 110592
    cudaFuncSetAttribute(gemm_y_f16,   cudaFuncAttributeMaxDynamicSharedMemorySize, SMEM_Y);
    cudaFuncSetAttribute(gemm_out_f16, cudaFuncAttributeMaxDynamicSharedMemorySize, SMEM_G);

    {
        dim3 grid(B, 8);
        prep_kernel<<<grid, 256>>>(x, proj_w);     // launch 1
    }
    attn_kernel<<<B, 256>>>(k_c);                  // launch 2
    {
        dim3 grid((NM + 255)/256, 4);
        mix_kernel<<<grid, 256>>>(v_c);            // launch 3
    }
    {
        dim3 grid(C/128, 2, B);                    // (6, 2, 128)
        gemm_y_f16<<<grid, 256, SMEM_Y>>>();       // launch 4 (profiled)
    }
    {
        dim3 grid(C/128, (B*N)/128);               // (6, 196)
        gemm_out_f16<<<grid, 256, SMEM_G>>>(proj_b, out);
    }
}

// round 16
// speedup vs baseline: 1.0604x; 1.0604x over previous
#include <cuda_runtime.h>
#include <cuda_fp16.h>
#include <math.h>

// Shapes (fixed by the problem)
#define B   128
#define N   196
#define C   768
#define CTR 64
#define NM  (N*N)          // 38416
#define VP  200            // padded token-dim length (halves), 16B-aligned rows
#define KH  64             // k-tile (halves) per pipeline stage
#define RS  72             // A smem row stride (halves); conflict-free ldmatrix
#define BS2 136            // B smem row stride for gemm_y trans tiles
// Dataflow: y = v @ x^T  (per batch, trans-ldmatrix on x[t][c]), out = y @ W^T + bias.

// Scratch (device globals: allocation-free rule)
__device__ float g_attn[B*CTR];
__device__ float g_qp[B*8*C];                    // partial column sums (7 used, pad 8)
__device__ __half g_xh[(size_t)B*N*C];           // fp16 x, natural [b][t][c]
__device__ __half g_wh[(size_t)C*C];             // fp16 proj_w [n][k]
__device__ __half g_v16[(size_t)B*N*VP];         // fp16 v, rows padded
__device__ __half g_y[(size_t)B*N*C];            // fp16 y = v@x^T, [b][t][c]

__device__ __forceinline__ void cp16(void* sdst, const void* gsrc, bool pred) {
    unsigned d = (unsigned)__cvta_generic_to_shared(sdst);
    int sz = pred ? 16 : 0;
    asm volatile("cp.async.cg.shared.global [%0], [%1], 16, %2;\n"
                 :: "r"(d), "l"(gsrc), "r"(sz));
}
__device__ __forceinline__ void cp_commit() {
    asm volatile("cp.async.commit_group;\n" ::: "memory");
}
__device__ __forceinline__ void cp_wait0() {
    asm volatile("cp.async.wait_group 0;\n" ::: "memory");
}
__device__ __forceinline__ void cp_wait1() {
    asm volatile("cp.async.wait_group 1;\n" ::: "memory");
}
__device__ __forceinline__ void cp_wait2() {
    asm volatile("cp.async.wait_group 2;\n" ::: "memory");
}

#define MMA_F16(acc, af, bf)                                                  \
    asm volatile(                                                             \
        "mma.sync.aligned.m16n8k16.row.col.f32.f16.f16.f32 "                  \
        "{%0,%1,%2,%3}, {%4,%5,%6,%7}, {%8,%9}, {%0,%1,%2,%3};"               \
        : "+f"((acc)[0]), "+f"((acc)[1]), "+f"((acc)[2]), "+f"((acc)[3])      \
        : "r"((af)[0]), "r"((af)[1]), "r"((af)[2]), "r"((af)[3]),             \
          "r"((bf)[0]), "r"((bf)[1]))

#define LDM_X4(r0, r1, r2, r3, addr)                                          \
    asm volatile(                                                             \
        "ldmatrix.sync.aligned.m8n8.x4.shared.b16 {%0,%1,%2,%3}, [%4];"       \
        : "=r"(r0), "=r"(r1), "=r"(r2), "=r"(r3) : "r"(addr))

#define LDM_X4T(r0, r1, r2, r3, addr)                                         \
    asm volatile(                                                             \
        "ldmatrix.sync.aligned.m8n8.x4.trans.shared.b16 {%0,%1,%2,%3}, [%4];" \
        : "=r"(r0), "=r"(r1), "=r"(r2), "=r"(r3) : "r"(addr))

// ---------------------------------------------------------------------------
// K1: fused pre-pass (R12 scalar form). grid (B, 8).
// ---------------------------------------------------------------------------
__global__ void prep_kernel(const float* __restrict__ x,
                            const float* __restrict__ w) {
    const int b = blockIdx.x, j = blockIdx.y;
    const int tid = threadIdx.x;
    if (j < 7) {
        const int r0 = j * 28;
        const float* xb = x + (size_t)b*N*C;
        for (int c = tid; c < C; c += 256) {
            float s = 0.f;
            #pragma unroll 4
            for (int n = 0; n < 28; n++) {
                size_t idx = (size_t)(r0+n)*C + c;
                float v = xb[idx];
                g_xh[(size_t)b*N*C + idx] = __float2half(v);
                s += v;
            }
            g_qp[((size_t)b*8 + j)*C + c] = s;
        }
    } else {
        const int base = b * (C*C / B);
        for (int i = tid; i < C*C / B; i += 256)
            g_wh[base + i] = __float2half(w[base + i]);
        const int p0 = b * N;
        for (int i = tid; i < N; i += 256)
            *(unsigned long long*)&g_v16[(size_t)(p0 + i)*VP + N] = 0ull;
    }
}

// ---------------------------------------------------------------------------
// K2: finish mean, cosine-sim vs k_c (coalesced), softmax
// ---------------------------------------------------------------------------
__global__ void attn_kernel(const float* __restrict__ k_c) {
    const int b = blockIdx.x;
    __shared__ float q[C];
    __shared__ float red[256];
    __shared__ float sdot[4][CTR];
    __shared__ float skn[4][CTR];
    __shared__ float logits[CTR];
    const int tid = threadIdx.x;

    for (int c = tid; c < C; c += 256) {
        float s = 0.f;
        #pragma unroll
        for (int j = 0; j < 7; j++) s += g_qp[((size_t)b*8 + j)*C + c];
        q[c] = s * (1.0f/N);
    }
    __syncthreads();

    float ps = 0.f;
    for (int c = tid; c < C; c += 256) ps += q[c]*q[c];
    red[tid] = ps;
    __syncthreads();
    for (int s = 128; s > 0; s >>= 1) {
        if (tid < s) red[tid] += red[tid+s];
        __syncthreads();
    }
    const float qinv = 1.0f / fmaxf(sqrtf(red[0]), 1e-12f);

    {
        const int c = tid & 63, g = tid >> 6;
        float dot = 0.f, kn = 0.f;
        for (int k = g; k < C; k += 4) {
            float kv = k_c[k*CTR + c];
            dot += q[k]*kv;
            kn  += kv*kv;
        }
        sdot[g][c] = dot;
        skn[g][c]  = kn;
    }
    __syncthreads();
    if (tid < CTR) {
        float d = sdot[0][tid] + sdot[1][tid] + sdot[2][tid] + sdot[3][tid];
        float n = skn[0][tid]  + skn[1][tid]  + skn[2][tid]  + skn[3][tid];
        float kinv = 1.0f / fmaxf(sqrtf(n), 1e-12f);
        logits[tid] = d * qinv * kinv * 0.03608439182435161f;
    }
    __syncthreads();

    if (tid == 0) {
        float mx = -1e30f;
        #pragma unroll
        for (int c = 0; c < CTR; c++) mx = fmaxf(mx, logits[c]);
        float sum = 0.f;
        #pragma unroll
        for (int c = 0; c < CTR; c++) { float e = expf(logits[c]-mx); logits[c] = e; sum += e; }
        float inv = 1.0f/sum;
        #pragma unroll
        for (int c = 0; c < CTR; c++) g_attn[b*CTR + c] = logits[c]*inv;
    }
}

// ---------------------------------------------------------------------------
// K3: v[b][n][m] = sum_c attn[b,c] * v_c[c][n][m]  (fp16, padded rows)
// ---------------------------------------------------------------------------
__global__ void mix_kernel(const float* __restrict__ v_c) {
    __shared__ float a_s[32*CTR];
    const int tid = threadIdx.x;
    const int g   = blockIdx.y;
    for (int i = tid; i < 32*CTR; i += 256) a_s[i] = g_attn[g*32*CTR + i];
    __syncthreads();

    const int nm = blockIdx.x*256 + tid;
    if (nm >= NM) return;
    const int n = nm / N, m = nm - n * N;

    float vr[CTR];
    #pragma unroll
    for (int c = 0; c < CTR; c++) vr[c] = v_c[(size_t)c*NM + nm];

    for (int b = 0; b < 32; b++) {
        const float* ap = a_s + b*CTR;
        float acc = 0.f;
        #pragma unroll
        for (int c = 0; c < CTR; c++) acc += ap[c]*vr[c];
        g_v16[((size_t)(g*32 + b)*N + n)*VP + m] = __float2half(acc);
    }
}

// ---------------------------------------------------------------------------
// K4: y[b] = v[b] @ x[b]^T   (R12-proven version, unchanged)
// ---------------------------------------------------------------------------
#define ASTG (128*RS)           // A halves per stage
#define BSTG (64*BS2)           // B halves per stage
#define YSTG (ASTG + BSTG)      // stage stride (halves)

__global__ __launch_bounds__(256, 2)
void gemm_y_f16() {
    extern __shared__ __half smh[];
    const int b = blockIdx.z;
    const __half* A = g_v16 + (size_t)b*N*VP;
    __half* Y = g_y + (size_t)b*N*C;

    const int tid  = threadIdx.x;
    const int lane = tid & 31;
    const int w    = tid >> 5;
    const int wm   = (w & 1) * 64;
    const int wn   = (w >> 1) * 32;
    const int bm   = blockIdx.y * 128;
    const int bn   = blockIdx.x * 128;

    const int lrow = tid >> 1;
    const int lko  = (tid & 1) * 32;
    const int brow = tid >> 2;
    const int bc0  = (tid & 3) * 32;

    const int gq = lane >> 2;
    const int tq = lane & 3;

    const int aRow  = wm + (lane & 7) + ((lane >> 3) & 1) * 8;
    const int aK    = (lane >> 4) * 8;
    const int bRowT = (lane & 7) + ((lane >> 3) & 1) * 8;
    const int bColT = (lane >> 4) * 8;

    float acc[4][4][4] = {};

    auto issue_load = [&](int s, int k0) {
        __half* As = smh + (size_t)s*YSTG;
        __half* Bs = As + ASTG;
        #pragma unroll
        for (int cch = 0; cch < 4; cch++) {
            int ko = lko + cch*8;
            cp16(&As[(size_t)lrow*RS + ko], &A[(size_t)(bm+lrow)*VP + k0 + ko],
                 (bm + lrow < N) && (k0 + ko + 8 <= VP));
        }
        const bool rok = (k0 + brow) < N;
        #pragma unroll
        for (int cch = 0; cch < 4; cch++) {
            int co = bc0 + cch*8;
            cp16(&Bs[(size_t)brow*BS2 + co],
                 &g_xh[((size_t)b*N + k0 + brow)*C + bn + co], rok);
        }
        cp_commit();
    };

    const int NITER = 4;
    issue_load(0, 0);
    issue_load(1, KH);

    for (int it = 0; it < NITER; it++) {
        const int cur = it % 3;
        if (it + 2 < NITER) cp_wait1(); else cp_wait0();
        __syncthreads();
        if (it + 2 < NITER) issue_load((it + 2) % 3, (it + 2) * KH);

        const __half* Ac = smh + (size_t)cur*YSTG;
        const __half* Bc = Ac + ASTG;
        const unsigned Acs = (unsigned)__cvta_generic_to_shared(Ac);
        const unsigned Bcs = (unsigned)__cvta_generic_to_shared(Bc);
        #pragma unroll
        for (int ks = 0; ks < 4; ks++) {
            const int kb = ks * 16;
            unsigned af[4][4], bf[4][2];
            #pragma unroll
            for (int mi = 0; mi < 4; mi++)
                LDM_X4(af[mi][0], af[mi][1], af[mi][2], af[mi][3],
                       Acs + (unsigned)(((aRow + mi*16)*RS + kb + aK) * 2));
            #pragma unroll
            for (int j = 0; j < 2; j++)
                LDM_X4T(bf[2*j][0], bf[2*j][1], bf[2*j+1][0], bf[2*j+1][1],
                        Bcs + (unsigned)(((kb + bRowT)*BS2 + wn + j*16 + bColT) * 2));
            #pragma unroll
            for (int mi = 0; mi < 4; mi++)
                #pragma unroll
                for (int nj = 0; nj < 4; nj++)
                    MMA_F16(acc[mi][nj], af[mi], bf[nj]);
        }
    }

    #pragma unroll
    for (int mi = 0; mi < 4; mi++) {
        #pragma unroll
        for (int nj = 0; nj < 4; nj++) {
            int r  = bm + wm + mi*16 + gq;
            int cc = bn + wn + nj*8 + 2*tq;
            if (r < N)
                *(__half2*)&Y[(size_t)r*C + cc] =
                    __halves2half2(__float2half(acc[mi][nj][0]), __float2half(acc[mi][nj][1]));
            if (r + 8 < N)
                *(__half2*)&Y[(size_t)(r+8)*C + cc] =
                    __halves2half2(__float2half(acc[mi][nj][2]), __float2half(acc[mi][nj][3]));
        }
    }
}

// ---------------------------------------------------------------------------
// K5 (NEW): out = y @ W^T + bias   (M=25088, N=768, K=768)
// 256m x 128n CTA tile, 512 threads (16 warps, 4m x 4n of 64x32), 1 CTA/SM,
// 4-stage KH=64 cp.async ring. y L2 re-reads: 6x -> 3x. Streaming OUT stores.
// ---------------------------------------------------------------------------
#define OASTG (256*RS)              // A halves per stage (256 rows)
#define OBSTG (128*RS)              // B halves per stage
#define OSTG  (OASTG + OBSTG)       // 27648 halves = 55296 B per stage

__global__ __launch_bounds__(512, 1)
void gemm_out_f16(const float* __restrict__ bias,
                  float* __restrict__ OUT) {
    extern __shared__ __half smh[];
    const int tid  = threadIdx.x;
    const int lane = tid & 31;
    const int w    = tid >> 5;            // 0..15
    const int wm   = (w & 3) * 64;        // 0,64,128,192
    const int wn   = (w >> 2) * 32;       // 0,32,64,96
    const int bm   = blockIdx.y * 256;
    const int bn   = blockIdx.x * 128;

    // A loader: 256 rows x 64 k; thread -> row tid>>1, k (tid&1)*32 + cch*8
    const int larow = tid >> 1;
    const int lako  = (tid & 1) * 32;
    // B loader: 128 rows x 64 k; thread -> row tid>>2, k (tid&3)*16 + j*8
    const int lbrow = tid >> 2;
    const int lbko  = (tid & 3) * 16;

    const int gq = lane >> 2;
    const int tq = lane & 3;

    const int aRow = wm + (lane & 7) + ((lane >> 3) & 1) * 8;
    const int aK   = (lane >> 4) * 8;
    const int bN   = wn + (lane & 7) + (lane >> 4) * 8;
    const int bK   = ((lane >> 3) & 1) * 8;

    float acc[4][4][4] = {};

    auto issue_load = [&](int s, int k0) {
        __half* As = smh + (size_t)s*OSTG;
        __half* Bs = As + OASTG;
        #pragma unroll
        for (int cch = 0; cch < 4; cch++) {
            int ko = lako + cch*8;
            cp16(&As[(size_t)larow*RS + ko], &g_y[(size_t)(bm+larow)*C + k0 + ko], true);
        }
        #pragma unroll
        for (int j = 0; j < 2; j++) {
            int ko = lbko + j*8;
            cp16(&Bs[(size_t)lbrow*RS + ko], &g_wh[(size_t)(bn+lbrow)*C + k0 + ko], true);
        }
        cp_commit();
    };

    const int NITER = C / KH;   // 12
    issue_load(0, 0);
    issue_load(1, KH);
    issue_load(2, 2*KH);

    for (int it = 0; it < NITER; it++) {
        const int cur = it & 3;
        if (it <= NITER - 3) cp_wait2();
        else if (it == NITER - 2) cp_wait1();
        else cp_wait0();
        __syncthreads();
        if (it + 3 < NITER) issue_load((it + 3) & 3, (it + 3) * KH);

        const __half* Ac = smh + (size_t)cur*OSTG;
        const __half* Bc = Ac + OASTG;
        const unsigned Acs = (unsigned)__cvta_generic_to_shared(Ac);
        const unsigned Bcs = (unsigned)__cvta_generic_to_shared(Bc);
        #pragma unroll
        for (int ks = 0; ks < 4; ks++) {
            const int kb = ks * 16;
            unsigned af[4][4], bf[4][2];
            #pragma unroll
            for (int mi = 0; mi < 4; mi++)
                LDM_X4(af[mi][0], af[mi][1], af[mi][2], af[mi][3],
                       Acs + (unsigned)(((aRow + mi*16)*RS + kb + aK) * 2));
            LDM_X4(bf[0][0], bf[0][1], bf[1][0], bf[1][1],
                   Bcs + (unsigned)((bN*RS + kb + bK) * 2));
            LDM_X4(bf[2][0], bf[2][1], bf[3][0], bf[3][1],
                   Bcs + (unsigned)(((bN + 16)*RS + kb + bK) * 2));
            #pragma unroll
            for (int mi = 0; mi < 4; mi++)
                #pragma unroll
                for (int nj = 0; nj < 4; nj++)
                    MMA_F16(acc[mi][nj], af[mi], bf[nj]);
        }
    }

    // epilogue: fp32 + bias, streaming stores (OUT never re-read)
    #pragma unroll
    for (int mi = 0; mi < 4; mi++) {
        #pragma unroll
        for (int nj = 0; nj < 4; nj++) {
            int r  = bm + wm + mi*16 + gq;
            int cc = bn + wn + nj*8 + 2*tq;
            float b0 = bias[cc], b1 = bias[cc+1];
            __stcs((float2*)&OUT[(size_t)r*C + cc],
                   make_float2(acc[mi][nj][0] + b0, acc[mi][nj][1] + b1));
            __stcs((float2*)&OUT[(size_t)(r+8)*C + cc],
                   make_float2(acc[mi][nj][2] + b0, acc[mi][nj][3] + b1));
        }
    }
}

// ---------------------------------------------------------------------------
extern "C" void kernel_launch(void* const* d_in, const int* in_sizes, int n_in,
                              void* d_out, int out_size) {
    const float* x      = (const float*)d_in[0];   // (128,196,768)
    const float* k_c    = (const float*)d_in[1];   // (768,64)
    const float* v_c    = (const float*)d_in[2];   // (64,196,196)
    const float* proj_w = (const float*)d_in[3];   // (768,768)
    const float* proj_b = (const float*)d_in[4];   // (768,)
    float* out = (float*)d_out;

    const int SMEM_Y = 3*YSTG * (int)sizeof(__half);        // 107520
    const int SMEM_O = 4*OSTG * (int)sizeof(__half);        // 221184
    cudaFuncSetAttribute(gemm_y_f16,   cudaFuncAttributeMaxDynamicSharedMemorySize, SMEM_Y);
    cudaFuncSetAttribute(gemm_out_f16, cudaFuncAttributeMaxDynamicSharedMemorySize, SMEM_O);

    {
        dim3 grid(B, 8);
        prep_kernel<<<grid, 256>>>(x, proj_w);     // launch 1
    }
    attn_kernel<<<B, 256>>>(k_c);                  // launch 2
    {
        dim3 grid((NM + 255)/256, 4);
        mix_kernel<<<grid, 256>>>(v_c);            // launch 3
    }
    {
        dim3 grid(C/128, 2, B);                    // (6, 2, 128)
        gemm_y_f16<<<grid, 256, SMEM_Y>>>();       // launch 4
    }
    {
        dim3 grid(C/128, (B*N)/256);               // (6, 98)
        gemm_out_f16<<<grid, 512, SMEM_O>>>(proj_b, out);
    }
}